// round 15
// baseline (speedup 1.0000x reference)
#include <cuda_runtime.h>
#include <cuda_fp16.h>
#include <math.h>
#include <stdint.h>

// Problem constants (fixed by the dataset)
#define N_NODES 100000
#define N_EDGES 1600000
#define F_IN    128
#define F_HID   64
#define F_OUT   64
#define CAP     64      // max in-degree bucket capacity (P(overflow) ~ 1e-13)

// ---------------- scratch (device globals; no allocations allowed) ----------
__device__ __half g_h16[N_NODES * 64];  // transformed features (gather side, fp16)
__device__ float  g_x2 [N_NODES * 64];  // layer-1 activations (input to GEMM2)
__device__ float  g_el [N_NODES];
__device__ float  g_er [N_NODES];
__device__ int    g_deg[N_NODES];
__device__ int    g_slots[N_NODES * CAP];  // src ids bucketed by dst
__device__ uint4  g_wfrag1[8 * 8 * 32];    // W1 fp16 hi/lo fragments (k16 chunks)
__device__ uint4  g_wfrag2[4 * 8 * 32];    // W2 fp16 hi/lo fragments

// ---------------- fp16 split helpers ----------------------------------------
__device__ __forceinline__ void split16(float x, __half& h, __half& l) {
    h = __float2half_rn(x);
    l = __float2half_rn(x - __half2float(h));
}

__device__ __forceinline__ uint32_t packh2(__half a, __half b) {
    __half2 p = __halves2half2(a, b);
    return *reinterpret_cast<uint32_t*>(&p);
}

// fp16 MMA m16n8k16, fp32 accumulate
__device__ __forceinline__ void mma_f16(float* d, const uint32_t* a, const uint32_t* b) {
    asm volatile(
        "mma.sync.aligned.m16n8k16.row.col.f32.f16.f16.f32 "
        "{%0,%1,%2,%3}, {%4,%5,%6,%7}, {%8,%9}, {%0,%1,%2,%3};"
        : "+f"(d[0]), "+f"(d[1]), "+f"(d[2]), "+f"(d[3])
        : "r"(a[0]), "r"(a[1]), "r"(a[2]), "r"(a[3]), "r"(b[0]), "r"(b[1]));
}

// ---------------- prep: zero degrees + W fragments (fused) ---------------------
__global__ void prep_kernel(const float* __restrict__ W1, const float* __restrict__ W2) {
    int i = blockIdx.x * blockDim.x + threadIdx.x;
    if (i < N_NODES) g_deg[i] = 0;
    if (i < 3072) {
        const float* W; uint4* dstp; int idx;
        if (i < 2048) { W = W1; dstp = g_wfrag1; idx = i; }
        else          { W = W2; dstp = g_wfrag2; idx = i - 2048; }
        int tig = idx & 3;
        int g   = (idx >> 2) & 7;
        int t   = (idx >> 5) & 7;
        int kc  = idx >> 8;
        int k0  = kc * 16 + 2 * tig;
        int n   = t * 8 + g;
        float w0 = W[(k0    ) * 64 + n];
        float w1 = W[(k0 + 1) * 64 + n];
        float w2 = W[(k0 + 8) * 64 + n];
        float w3 = W[(k0 + 9) * 64 + n];
        __half h0, l0, h1, l1, h2, l2, h3, l3;
        split16(w0, h0, l0); split16(w1, h1, l1);
        split16(w2, h2, l2); split16(w3, h3, l3);
        uint4 v;
        v.x = packh2(h0, h1);
        v.y = packh2(h2, h3);
        v.z = packh2(l0, l1);
        v.w = packh2(l2, l3);
        dstp[idx] = v;
    }
}

// ---------------- fused GEMM + attention dots (+ edge bucketing in layer 1) ----
template <int K, bool DO_BUCKET>
__global__ void __launch_bounds__(256, 4)
gemm_attn_kernel(const float* __restrict__ X, const uint4* __restrict__ wfrag,
                 const float* __restrict__ attn_l, const float* __restrict__ attn_r,
                 __half* __restrict__ H16,
                 const int* __restrict__ src, const int* __restrict__ dst) {
    constexpr int XS = (K == 128) ? 36 : 20;   // uint4 row stride, == 4 mod 8
    __shared__ uint4 xs[64 * XS];
    __shared__ float s_al[64], s_ar[64];
    __shared__ float s_el[64][2], s_er[64][2];

    const int tid  = threadIdx.x;
    const int warp = tid >> 5;
    const int lane = tid & 31;
    const int gr   = lane >> 2;
    const int q4   = lane & 3;
    const int rg   = warp >> 1;
    const int ch   = warp & 1;
    const int row0 = blockIdx.x * 64;

    if (tid < 64) { s_al[tid] = attn_l[tid]; s_ar[tid] = attn_r[tid]; }

    #pragma unroll
    for (int it = 0; it < K / 32; it++) {
        int item = it * 256 + tid;
        int r   = item / (K / 8);
        int rem = item % (K / 8);
        int kc  = rem >> 1;
        int a   = rem & 1;
        float4 v0 = make_float4(0.f, 0.f, 0.f, 0.f), v1 = v0;
        if (row0 + r < N_NODES) {
            const float* xp = X + (size_t)(row0 + r) * K + kc * 16 + 4 * a;
            v0 = *(const float4*)xp;
            v1 = *(const float4*)(xp + 8);
        }
        __half h00, l00, h01, l01, h02, l02, h03, l03;
        __half h10, l10, h11, l11, h12, l12, h13, l13;
        split16(v0.x, h00, l00); split16(v0.y, h01, l01);
        split16(v0.z, h02, l02); split16(v0.w, h03, l03);
        split16(v1.x, h10, l10); split16(v1.y, h11, l11);
        split16(v1.z, h12, l12); split16(v1.w, h13, l13);
        uint4 uA, uB;
        uA.x = packh2(h00, h01); uA.y = packh2(h10, h11);
        uA.z = packh2(l00, l01); uA.w = packh2(l10, l11);
        uB.x = packh2(h02, h03); uB.y = packh2(h12, h13);
        uB.z = packh2(l02, l03); uB.w = packh2(l12, l13);
        int au = r * XS + kc * 4 + 2 * a;
        xs[au]     = uA;
        xs[au + 1] = uB;
    }
    __syncthreads();

    // edge bucketing for this block's 1024-edge slice (layer 1 only);
    // independent of GEMM data, latency overlaps the MMA loop below.
    if (DO_BUCKET) {
        int e0 = blockIdx.x * 1024 + tid;
        #pragma unroll
        for (int u = 0; u < 4; u++) {
            int i = e0 + u * 256;
            if (i < N_EDGES) {
                int dd = __ldg(&dst[i]);
                int p = atomicAdd(&g_deg[dd], 1);
                if (p < CAP) g_slots[dd * CAP + p] = __ldg(&src[i]);
            }
        }
    }

    float acc[4][4];
    #pragma unroll
    for (int t = 0; t < 4; t++)
        #pragma unroll
        for (int i = 0; i < 4; i++) acc[t][i] = 0.f;

    #pragma unroll
    for (int kc = 0; kc < K / 16; kc++) {
        int ia = (rg * 16 + gr) * XS + kc * 4 + q4;
        uint4 u0 = xs[ia];
        uint4 u1 = xs[ia + 8 * XS];
        uint32_t ah[4] = {u0.x, u1.x, u0.y, u1.y};
        uint32_t al[4] = {u0.z, u1.z, u0.w, u1.w};
        const uint4* wrow = wfrag + kc * 256 + ch * 128 + lane;
        #pragma unroll
        for (int t = 0; t < 4; t++) {
            uint4 wv = __ldg(wrow + t * 32);
            uint32_t bh[2] = {wv.x, wv.y};
            uint32_t bl[2] = {wv.z, wv.w};
            mma_f16(acc[t], ah, bh);
            mma_f16(acc[t], al, bh);
            mma_f16(acc[t], ah, bl);
        }
    }

    const int rl_lo = rg * 16 + gr;
    const int rl_hi = rl_lo + 8;
    const int r_lo  = row0 + rl_lo;
    const int r_hi  = row0 + rl_hi;
    float el_lo = 0.f, er_lo = 0.f, el_hi = 0.f, er_hi = 0.f;
    #pragma unroll
    for (int t = 0; t < 4; t++) {
        int n = ch * 32 + t * 8 + 2 * q4;
        float al0 = s_al[n], al1 = s_al[n + 1];
        float ar0 = s_ar[n], ar1 = s_ar[n + 1];
        el_lo += acc[t][0] * al0 + acc[t][1] * al1;
        er_lo += acc[t][0] * ar0 + acc[t][1] * ar1;
        el_hi += acc[t][2] * al0 + acc[t][3] * al1;
        er_hi += acc[t][2] * ar0 + acc[t][3] * ar1;
        if (r_lo < N_NODES)
            *(__half2*)(H16 + (size_t)r_lo * 64 + n) = __floats2half2_rn(acc[t][0], acc[t][1]);
        if (r_hi < N_NODES)
            *(__half2*)(H16 + (size_t)r_hi * 64 + n) = __floats2half2_rn(acc[t][2], acc[t][3]);
    }
    #pragma unroll
    for (int o = 1; o <= 2; o <<= 1) {
        el_lo += __shfl_xor_sync(0xFFFFFFFFu, el_lo, o);
        er_lo += __shfl_xor_sync(0xFFFFFFFFu, er_lo, o);
        el_hi += __shfl_xor_sync(0xFFFFFFFFu, el_hi, o);
        er_hi += __shfl_xor_sync(0xFFFFFFFFu, er_hi, o);
    }
    if (q4 == 0) {
        s_el[rl_lo][ch] = el_lo; s_er[rl_lo][ch] = er_lo;
        s_el[rl_hi][ch] = el_hi; s_er[rl_hi][ch] = er_hi;
    }
    __syncthreads();
    if (tid < 64 && row0 + tid < N_NODES) {
        g_el[row0 + tid] = s_el[tid][0] + s_el[tid][1];
        g_er[row0 + tid] = s_er[tid][0] + s_er[tid][1];
    }
}

// ---------------- softmax-aggregate: warp per dst node ----------------------
// No max-subtraction (softmax shift-invariant; logits |e| <~ 7 << 88).
// Fast path (d <= 32): batch-0 feature gathers are PREFETCHED before the
// logit chain (el gather + exp + shfl) so their ~600-cycle latency overlaps it.
template <bool RELU>
__global__ void aggregate_kernel(const float* __restrict__ bias,
                                 float* __restrict__ out) {
    int gw   = (blockIdx.x * blockDim.x + threadIdx.x) >> 5;
    int lane = threadIdx.x & 31;
    if (gw >= N_NODES) return;

    const int d = min(g_deg[gw], CAP);
    const int base = gw * CAP;
    const float ern = g_er[gw];

    if (d <= 32) {
        const int g = lane >> 3;      // edge subgroup 0..3
        const int cc = lane & 7;      // col octet 0..7

        // load slot ids, broadcast batch-0 src ids, ISSUE feature gathers now
        int sv = (lane < d) ? __ldg(&g_slots[base + lane]) : 0;
        int svj0[4]; uint4 hv0[4];
        #pragma unroll
        for (int u = 0; u < 4; u++)
            svj0[u] = __shfl_sync(0xFFFFFFFFu, sv, u * 4 + g);
        #pragma unroll
        for (int u = 0; u < 4; u++)
            hv0[u] = __ldg((const uint4*)(g_h16 + (size_t)svj0[u] * 64) + cc);

        // logit chain overlaps the in-flight gathers above
        float ex = 0.f;
        if (lane < d) {
            float ev = __ldg(&g_el[sv]) + ern;
            ev = ev >= 0.f ? ev : 0.2f * ev;
            ex = __expf(ev);
        }
        float exj0[4];
        #pragma unroll
        for (int u = 0; u < 4; u++)
            exj0[u] = __shfl_sync(0xFFFFFFFFu, ex, u * 4 + g);

        float a[8];
        #pragma unroll
        for (int u = 0; u < 8; u++) a[u] = 0.f;

        // batch 0: edges 0..15 (exj=0 pads)
        #pragma unroll
        for (int u = 0; u < 4; u++) {
            const __half2* hp = (const __half2*)&hv0[u];
            #pragma unroll
            for (int v = 0; v < 4; v++) {
                float2 f = __half22float2(hp[v]);
                a[2 * v]     = fmaf(exj0[u], f.x, a[2 * v]);
                a[2 * v + 1] = fmaf(exj0[u], f.y, a[2 * v + 1]);
            }
        }
        if (d > 16) {   // batch 1: edges 16..31
            float exj[4]; int svj[4]; uint4 hv[4];
            #pragma unroll
            for (int u = 0; u < 4; u++) {
                int j = 16 + u * 4 + g;
                exj[u] = __shfl_sync(0xFFFFFFFFu, ex, j);
                svj[u] = __shfl_sync(0xFFFFFFFFu, sv, j);
            }
            #pragma unroll
            for (int u = 0; u < 4; u++)
                hv[u] = __ldg((const uint4*)(g_h16 + (size_t)svj[u] * 64) + cc);
            #pragma unroll
            for (int u = 0; u < 4; u++) {
                const __half2* hp = (const __half2*)&hv[u];
                #pragma unroll
                for (int v = 0; v < 4; v++) {
                    float2 f = __half22float2(hp[v]);
                    a[2 * v]     = fmaf(exj[u], f.x, a[2 * v]);
                    a[2 * v + 1] = fmaf(exj[u], f.y, a[2 * v + 1]);
                }
            }
        }
        // combine subgroups (lanes differing in bits 3,4 share the same cols)
        #pragma unroll
        for (int u = 0; u < 8; u++) {
            a[u] += __shfl_xor_sync(0xFFFFFFFFu, a[u], 8);
            a[u] += __shfl_xor_sync(0xFFFFFFFFu, a[u], 16);
        }
        float s = ex;
        #pragma unroll
        for (int o = 16; o; o >>= 1) s += __shfl_xor_sync(0xFFFFFFFFu, s, o);
        float inv = (d > 0) ? 1.0f / s : 0.0f;

        if (g == 0) {   // lanes 0..7 write 8 cols each
            float4 b0 = __ldg((const float4*)bias + cc * 2);
            float4 b1 = __ldg((const float4*)bias + cc * 2 + 1);
            float o0 = fmaf(a[0], inv, b0.x), o1 = fmaf(a[1], inv, b0.y);
            float o2 = fmaf(a[2], inv, b0.z), o3 = fmaf(a[3], inv, b0.w);
            float o4 = fmaf(a[4], inv, b1.x), o5 = fmaf(a[5], inv, b1.y);
            float o6 = fmaf(a[6], inv, b1.z), o7 = fmaf(a[7], inv, b1.w);
            if (RELU) {
                o0 = fmaxf(o0, 0.f); o1 = fmaxf(o1, 0.f);
                o2 = fmaxf(o2, 0.f); o3 = fmaxf(o3, 0.f);
                o4 = fmaxf(o4, 0.f); o5 = fmaxf(o5, 0.f);
                o6 = fmaxf(o6, 0.f); o7 = fmaxf(o7, 0.f);
            }
            float4* op = (float4*)(out + (size_t)gw * 64 + cc * 8);
            op[0] = make_float4(o0, o1, o2, o3);
            op[1] = make_float4(o4, o5, o6, o7);
        }
    } else {
        // generic path (rare heavy nodes), lane = 2 cols; no max-subtraction
        const __half2* __restrict__ h2 = (const __half2*)g_h16;
        float s = 0.f, a0 = 0.f, a1 = 0.f;
        for (int b0i = 0; b0i < d; b0i += 32) {
            int i = b0i + lane;
            float ex = 0.f;
            int sv = 0;
            if (i < d) {
                sv = __ldg(&g_slots[base + i]);
                float evx = __ldg(&g_el[sv]) + ern;
                evx = evx >= 0.f ? evx : 0.2f * evx;
                ex = __expf(evx);
            }
            s += ex;
            int cnt = min(32, d - b0i);
            for (int j = 0; j < cnt; j++) {
                float exj = __shfl_sync(0xFFFFFFFFu, ex, j);
                int   svj = __shfl_sync(0xFFFFFFFFu, sv, j);
                float2 f = __half22float2(h2[(size_t)svj * 32 + lane]);
                a0 = fmaf(exj, f.x, a0);
                a1 = fmaf(exj, f.y, a1);
            }
        }
        #pragma unroll
        for (int o = 16; o; o >>= 1) s += __shfl_xor_sync(0xFFFFFFFFu, s, o);
        float inv = 1.0f / s;
        float2 bv = *(const float2*)(bias + lane * 2);
        float o0 = fmaf(a0, inv, bv.x);
        float o1 = fmaf(a1, inv, bv.y);
        if (RELU) { o0 = fmaxf(o0, 0.f); o1 = fmaxf(o1, 0.f); }
        *(float2*)(out + (size_t)gw * 64 + lane * 2) = make_float2(o0, o1);
    }
}

// ---------------- launch ----------------------------------------------------
extern "C" void kernel_launch(void* const* d_in, const int* in_sizes, int n_in,
                              void* d_out, int out_size) {
    const float* features = (const float*)d_in[0];
    // d_in[1] edge_weights: unused (matches reference)
    const int*   src      = (const int*)d_in[2];
    const int*   dst      = (const int*)d_in[3];
    const float* W1       = (const float*)d_in[4];
    const float* attn_l1  = (const float*)d_in[5];
    const float* attn_r1  = (const float*)d_in[6];
    const float* bias1    = (const float*)d_in[7];
    const float* W2       = (const float*)d_in[8];
    const float* attn_l2  = (const float*)d_in[9];
    const float* attn_r2  = (const float*)d_in[10];
    const float* bias2    = (const float*)d_in[11];
    float* out = (float*)d_out;

    __half* g_h16_ptr; cudaGetSymbolAddress((void**)&g_h16_ptr, g_h16);
    float*  g_x2_ptr;  cudaGetSymbolAddress((void**)&g_x2_ptr,  g_x2);
    uint4*  wf1_ptr;   cudaGetSymbolAddress((void**)&wf1_ptr,   g_wfrag1);
    uint4*  wf2_ptr;   cudaGetSymbolAddress((void**)&wf2_ptr,   g_wfrag2);

    const int NBp = (N_NODES + 255) / 256;   // 391
    const int WARP_GRID = (N_NODES * 32 + 255) / 256;  // 12500
    const int GEMM_GRID = (N_NODES + 63) / 64;         // 1563

    // --- prep (zero degrees + W fragments) ---
    prep_kernel<<<NBp, 256>>>(W1, W2);

    // --- layer 1: GEMM + attn dots + edge bucketing, all in one launch ---
    gemm_attn_kernel<F_IN, true><<<GEMM_GRID, 256>>>(
        features, wf1_ptr, attn_l1, attn_r1, g_h16_ptr, src, dst);
    aggregate_kernel<true><<<WARP_GRID, 256>>>(bias1, g_x2_ptr);

    // --- layer 2 ---
    gemm_attn_kernel<F_HID, false><<<GEMM_GRID, 256>>>(
        g_x2_ptr, wf2_ptr, attn_l2, attn_r2, g_h16_ptr, nullptr, nullptr);
    aggregate_kernel<false><<<WARP_GRID, 256>>>(bias2, out);
}

// round 16
// speedup vs baseline: 1.0539x; 1.0539x over previous
#include <cuda_runtime.h>
#include <cuda_fp16.h>
#include <math.h>
#include <stdint.h>

// Problem constants (fixed by the dataset)
#define N_NODES 100000
#define N_EDGES 1600000
#define F_IN    128
#define F_HID   64
#define F_OUT   64
#define CAP     64      // max in-degree bucket capacity (P(overflow) ~ 1e-13)

// ---------------- scratch (device globals; no allocations allowed) ----------
__device__ __half g_h16[N_NODES * 64];  // transformed features (gather side, fp16)
__device__ __half g_x2h[N_NODES * 64];  // layer-1 activations (fp16, input to GEMM2)
__device__ float  g_el [N_NODES];
__device__ float  g_er [N_NODES];
__device__ int    g_deg[N_NODES];
__device__ int    g_slots[N_NODES * CAP];  // src ids bucketed by dst
__device__ uint4  g_wfrag1[8 * 8 * 32];    // W1 fp16 hi/lo fragments (k16 chunks)
__device__ uint4  g_wfrag2[4 * 8 * 32];    // W2 fp16 hi/lo fragments

// ---------------- fp16 split helpers ----------------------------------------
__device__ __forceinline__ void split16(float x, __half& h, __half& l) {
    h = __float2half_rn(x);
    l = __float2half_rn(x - __half2float(h));
}

__device__ __forceinline__ uint32_t packh2(__half a, __half b) {
    __half2 p = __halves2half2(a, b);
    return *reinterpret_cast<uint32_t*>(&p);
}

// fp16 MMA m16n8k16, fp32 accumulate
__device__ __forceinline__ void mma_f16(float* d, const uint32_t* a, const uint32_t* b) {
    asm volatile(
        "mma.sync.aligned.m16n8k16.row.col.f32.f16.f16.f32 "
        "{%0,%1,%2,%3}, {%4,%5,%6,%7}, {%8,%9}, {%0,%1,%2,%3};"
        : "+f"(d[0]), "+f"(d[1]), "+f"(d[2]), "+f"(d[3])
        : "r"(a[0]), "r"(a[1]), "r"(a[2]), "r"(a[3]), "r"(b[0]), "r"(b[1]));
}

// ---------------- prep: zero degrees + W fragments (fused) ---------------------
__global__ void prep_kernel(const float* __restrict__ W1, const float* __restrict__ W2) {
    int i = blockIdx.x * blockDim.x + threadIdx.x;
    if (i < N_NODES) g_deg[i] = 0;
    if (i < 3072) {
        const float* W; uint4* dstp; int idx;
        if (i < 2048) { W = W1; dstp = g_wfrag1; idx = i; }
        else          { W = W2; dstp = g_wfrag2; idx = i - 2048; }
        int tig = idx & 3;
        int g   = (idx >> 2) & 7;
        int t   = (idx >> 5) & 7;
        int kc  = idx >> 8;
        int k0  = kc * 16 + 2 * tig;
        int n   = t * 8 + g;
        float w0 = W[(k0    ) * 64 + n];
        float w1 = W[(k0 + 1) * 64 + n];
        float w2 = W[(k0 + 8) * 64 + n];
        float w3 = W[(k0 + 9) * 64 + n];
        __half h0, l0, h1, l1, h2, l2, h3, l3;
        split16(w0, h0, l0); split16(w1, h1, l1);
        split16(w2, h2, l2); split16(w3, h3, l3);
        uint4 v;
        v.x = packh2(h0, h1);
        v.y = packh2(h2, h3);
        v.z = packh2(l0, l1);
        v.w = packh2(l2, l3);
        dstp[idx] = v;
    }
}

// ---------------- fused GEMM + attention dots ----------------------------------
// HALF_IN: X is fp16 -> lo(X)=0 exactly, so the al*bh MMA term vanishes
// (2 MMAs/step instead of 3) and staging is a pure layout shuffle.
// fp32 path: R8-proven hi/lo split (3 MMAs/step).
// DO_BUCKET: block additionally buckets 1024 edges under the MMA loop.
template <int K, bool DO_BUCKET, bool HALF_IN>
__global__ void __launch_bounds__(256, 4)
gemm_attn_kernel(const void* __restrict__ Xv, const uint4* __restrict__ wfrag,
                 const float* __restrict__ attn_l, const float* __restrict__ attn_r,
                 __half* __restrict__ H16,
                 const int* __restrict__ src, const int* __restrict__ dst) {
    constexpr int XS = (K == 128) ? 36 : 20;   // uint4 row stride (fp32 path)
    // HALF_IN uses uint2 rows of stride 20 (== 4 mod 16 -> conflict-free LDS.64)
    __shared__ uint4 xs[HALF_IN ? (64 * 20 / 2) : (64 * XS)];
    __shared__ float s_al[64], s_ar[64];
    __shared__ float s_el[64][2], s_er[64][2];

    const int tid  = threadIdx.x;
    const int warp = tid >> 5;
    const int lane = tid & 31;
    const int gr   = lane >> 2;
    const int q4   = lane & 3;
    const int rg   = warp >> 1;
    const int ch   = warp & 1;
    const int row0 = blockIdx.x * 64;

    if (tid < 64) { s_al[tid] = attn_l[tid]; s_ar[tid] = attn_r[tid]; }

    if (HALF_IN) {
        // stage fp16 X: thread = one (row, k16-chunk); pure layout shuffle
        const __half* X = (const __half*)Xv;
        uint2* xs2 = (uint2*)xs;
        int r  = tid >> 2;
        int kc = tid & 3;
        uint4 u0 = make_uint4(0, 0, 0, 0), u1 = u0;
        if (row0 + r < N_NODES) {
            const uint4* xp = (const uint4*)(X + (size_t)(row0 + r) * 64 + kc * 16);
            u0 = __ldg(xp);
            u1 = __ldg(xp + 1);
        }
        uint4* d4 = (uint4*)&xs2[r * 20 + kc * 4];
        d4[0] = make_uint4(u0.x, u1.x, u0.y, u1.y);
        d4[1] = make_uint4(u0.z, u1.z, u0.w, u1.w);
    } else {
        const float* X = (const float*)Xv;
        #pragma unroll
        for (int it = 0; it < K / 32; it++) {
            int item = it * 256 + tid;
            int r   = item / (K / 8);
            int rem = item % (K / 8);
            int kc  = rem >> 1;
            int a   = rem & 1;
            float4 v0 = make_float4(0.f, 0.f, 0.f, 0.f), v1 = v0;
            if (row0 + r < N_NODES) {
                const float* xp = X + (size_t)(row0 + r) * K + kc * 16 + 4 * a;
                v0 = *(const float4*)xp;
                v1 = *(const float4*)(xp + 8);
            }
            __half h00, l00, h01, l01, h02, l02, h03, l03;
            __half h10, l10, h11, l11, h12, l12, h13, l13;
            split16(v0.x, h00, l00); split16(v0.y, h01, l01);
            split16(v0.z, h02, l02); split16(v0.w, h03, l03);
            split16(v1.x, h10, l10); split16(v1.y, h11, l11);
            split16(v1.z, h12, l12); split16(v1.w, h13, l13);
            uint4 uA, uB;
            uA.x = packh2(h00, h01); uA.y = packh2(h10, h11);
            uA.z = packh2(l00, l01); uA.w = packh2(l10, l11);
            uB.x = packh2(h02, h03); uB.y = packh2(h12, h13);
            uB.z = packh2(l02, l03); uB.w = packh2(l12, l13);
            int au = r * XS + kc * 4 + 2 * a;
            xs[au]     = uA;
            xs[au + 1] = uB;
        }
    }
    __syncthreads();

    // edge bucketing for this block's 1024-edge slice (layer 1 only)
    if (DO_BUCKET) {
        int e0 = blockIdx.x * 1024 + tid;
        #pragma unroll
        for (int u = 0; u < 4; u++) {
            int i = e0 + u * 256;
            if (i < N_EDGES) {
                int dd = __ldg(&dst[i]);
                int p = atomicAdd(&g_deg[dd], 1);
                if (p < CAP) g_slots[dd * CAP + p] = __ldg(&src[i]);
            }
        }
    }

    float acc[4][4];
    #pragma unroll
    for (int t = 0; t < 4; t++)
        #pragma unroll
        for (int i = 0; i < 4; i++) acc[t][i] = 0.f;

    if (HALF_IN) {
        const uint2* xs2 = (const uint2*)xs;
        #pragma unroll
        for (int kc = 0; kc < K / 16; kc++) {
            int ia = (rg * 16 + gr) * 20 + kc * 4 + q4;
            uint2 u0 = xs2[ia];
            uint2 u1 = xs2[ia + 8 * 20];
            uint32_t ah[4] = {u0.x, u1.x, u0.y, u1.y};
            const uint4* wrow = wfrag + kc * 256 + ch * 128 + lane;
            #pragma unroll
            for (int t = 0; t < 4; t++) {
                uint4 wv = __ldg(wrow + t * 32);
                uint32_t bh[2] = {wv.x, wv.y};
                uint32_t bl[2] = {wv.z, wv.w};
                mma_f16(acc[t], ah, bh);
                mma_f16(acc[t], ah, bl);
            }
        }
    } else {
        #pragma unroll
        for (int kc = 0; kc < K / 16; kc++) {
            int ia = (rg * 16 + gr) * XS + kc * 4 + q4;
            uint4 u0 = xs[ia];
            uint4 u1 = xs[ia + 8 * XS];
            uint32_t ah[4] = {u0.x, u1.x, u0.y, u1.y};
            uint32_t al[4] = {u0.z, u1.z, u0.w, u1.w};
            const uint4* wrow = wfrag + kc * 256 + ch * 128 + lane;
            #pragma unroll
            for (int t = 0; t < 4; t++) {
                uint4 wv = __ldg(wrow + t * 32);
                uint32_t bh[2] = {wv.x, wv.y};
                uint32_t bl[2] = {wv.z, wv.w};
                mma_f16(acc[t], ah, bh);
                mma_f16(acc[t], al, bh);
                mma_f16(acc[t], ah, bl);
            }
        }
    }

    const int rl_lo = rg * 16 + gr;
    const int rl_hi = rl_lo + 8;
    const int r_lo  = row0 + rl_lo;
    const int r_hi  = row0 + rl_hi;
    float el_lo = 0.f, er_lo = 0.f, el_hi = 0.f, er_hi = 0.f;
    #pragma unroll
    for (int t = 0; t < 4; t++) {
        int n = ch * 32 + t * 8 + 2 * q4;
        float al0 = s_al[n], al1 = s_al[n + 1];
        float ar0 = s_ar[n], ar1 = s_ar[n + 1];
        el_lo += acc[t][0] * al0 + acc[t][1] * al1;
        er_lo += acc[t][0] * ar0 + acc[t][1] * ar1;
        el_hi += acc[t][2] * al0 + acc[t][3] * al1;
        er_hi += acc[t][2] * ar0 + acc[t][3] * ar1;
        if (r_lo < N_NODES)
            *(__half2*)(H16 + (size_t)r_lo * 64 + n) = __floats2half2_rn(acc[t][0], acc[t][1]);
        if (r_hi < N_NODES)
            *(__half2*)(H16 + (size_t)r_hi * 64 + n) = __floats2half2_rn(acc[t][2], acc[t][3]);
    }
    #pragma unroll
    for (int o = 1; o <= 2; o <<= 1) {
        el_lo += __shfl_xor_sync(0xFFFFFFFFu, el_lo, o);
        er_lo += __shfl_xor_sync(0xFFFFFFFFu, er_lo, o);
        el_hi += __shfl_xor_sync(0xFFFFFFFFu, el_hi, o);
        er_hi += __shfl_xor_sync(0xFFFFFFFFu, er_hi, o);
    }
    if (q4 == 0) {
        s_el[rl_lo][ch] = el_lo; s_er[rl_lo][ch] = er_lo;
        s_el[rl_hi][ch] = el_hi; s_er[rl_hi][ch] = er_hi;
    }
    __syncthreads();
    if (tid < 64 && row0 + tid < N_NODES) {
        g_el[row0 + tid] = s_el[tid][0] + s_el[tid][1];
        g_er[row0 + tid] = s_er[tid][0] + s_er[tid][1];
    }
}

// ---------------- softmax-aggregate: warp per dst node (R14-proven) -------------
// No max-subtraction (softmax shift-invariant; logits |e| <~ 7 << 88).
// OUT_HALF: write results as fp16 (layer-1 activations feeding GEMM2).
template <bool RELU, bool OUT_HALF>
__global__ void aggregate_kernel(const float* __restrict__ bias,
                                 void* __restrict__ outv) {
    int gw   = (blockIdx.x * blockDim.x + threadIdx.x) >> 5;
    int lane = threadIdx.x & 31;
    if (gw >= N_NODES) return;

    const int d = min(g_deg[gw], CAP);
    const int base = gw * CAP;
    const float ern = g_er[gw];

    if (d <= 32) {
        // phase 1: lane = edge index; ex = exp(leaky(el+er)) directly
        int sv = (lane < d) ? __ldg(&g_slots[base + lane]) : 0;
        float ex = 0.f;
        if (lane < d) {
            float ev = __ldg(&g_el[sv]) + ern;
            ev = ev >= 0.f ? ev : 0.2f * ev;
            ex = __expf(ev);
        }

        // phase 2: batches of 16 edges, 4 loads/lane in flight
        const int g = lane >> 3;      // edge subgroup 0..3
        const int cc = lane & 7;      // col octet 0..7
        float a[8];
        #pragma unroll
        for (int u = 0; u < 8; u++) a[u] = 0.f;

        {   // batch 0: edges 0..15 (always; exj=0 pads)
            float exj[4]; int svj[4]; uint4 hv[4];
            #pragma unroll
            for (int u = 0; u < 4; u++) {
                int j = u * 4 + g;
                exj[u] = __shfl_sync(0xFFFFFFFFu, ex, j);
                svj[u] = __shfl_sync(0xFFFFFFFFu, sv, j);
            }
            #pragma unroll
            for (int u = 0; u < 4; u++)
                hv[u] = __ldg((const uint4*)(g_h16 + (size_t)svj[u] * 64) + cc);
            #pragma unroll
            for (int u = 0; u < 4; u++) {
                const __half2* hp = (const __half2*)&hv[u];
                #pragma unroll
                for (int v = 0; v < 4; v++) {
                    float2 f = __half22float2(hp[v]);
                    a[2 * v]     = fmaf(exj[u], f.x, a[2 * v]);
                    a[2 * v + 1] = fmaf(exj[u], f.y, a[2 * v + 1]);
                }
            }
        }
        if (d > 16) {   // batch 1: edges 16..31
            float exj[4]; int svj[4]; uint4 hv[4];
            #pragma unroll
            for (int u = 0; u < 4; u++) {
                int j = 16 + u * 4 + g;
                exj[u] = __shfl_sync(0xFFFFFFFFu, ex, j);
                svj[u] = __shfl_sync(0xFFFFFFFFu, sv, j);
            }
            #pragma unroll
            for (int u = 0; u < 4; u++)
                hv[u] = __ldg((const uint4*)(g_h16 + (size_t)svj[u] * 64) + cc);
            #pragma unroll
            for (int u = 0; u < 4; u++) {
                const __half2* hp = (const __half2*)&hv[u];
                #pragma unroll
                for (int v = 0; v < 4; v++) {
                    float2 f = __half22float2(hp[v]);
                    a[2 * v]     = fmaf(exj[u], f.x, a[2 * v]);
                    a[2 * v + 1] = fmaf(exj[u], f.y, a[2 * v + 1]);
                }
            }
        }
        // combine subgroups (lanes differing in bits 3,4 share the same cols)
        #pragma unroll
        for (int u = 0; u < 8; u++) {
            a[u] += __shfl_xor_sync(0xFFFFFFFFu, a[u], 8);
            a[u] += __shfl_xor_sync(0xFFFFFFFFu, a[u], 16);
        }
        float s = ex;
        #pragma unroll
        for (int o = 16; o; o >>= 1) s += __shfl_xor_sync(0xFFFFFFFFu, s, o);
        float inv = (d > 0) ? 1.0f / s : 0.0f;

        if (g == 0) {   // lanes 0..7 write 8 cols each
            float4 b0 = __ldg((const float4*)bias + cc * 2);
            float4 b1 = __ldg((const float4*)bias + cc * 2 + 1);
            float o0 = fmaf(a[0], inv, b0.x), o1 = fmaf(a[1], inv, b0.y);
            float o2 = fmaf(a[2], inv, b0.z), o3 = fmaf(a[3], inv, b0.w);
            float o4 = fmaf(a[4], inv, b1.x), o5 = fmaf(a[5], inv, b1.y);
            float o6 = fmaf(a[6], inv, b1.z), o7 = fmaf(a[7], inv, b1.w);
            if (RELU) {
                o0 = fmaxf(o0, 0.f); o1 = fmaxf(o1, 0.f);
                o2 = fmaxf(o2, 0.f); o3 = fmaxf(o3, 0.f);
                o4 = fmaxf(o4, 0.f); o5 = fmaxf(o5, 0.f);
                o6 = fmaxf(o6, 0.f); o7 = fmaxf(o7, 0.f);
            }
            if (OUT_HALF) {
                __half* oh = (__half*)outv;
                uint4 w;
                __half2* wp = (__half2*)&w;
                wp[0] = __floats2half2_rn(o0, o1);
                wp[1] = __floats2half2_rn(o2, o3);
                wp[2] = __floats2half2_rn(o4, o5);
                wp[3] = __floats2half2_rn(o6, o7);
                *(uint4*)(oh + (size_t)gw * 64 + cc * 8) = w;
            } else {
                float* of = (float*)outv;
                float4* op = (float4*)(of + (size_t)gw * 64 + cc * 8);
                op[0] = make_float4(o0, o1, o2, o3);
                op[1] = make_float4(o4, o5, o6, o7);
            }
        }
    } else {
        // generic path (rare heavy nodes), lane = 2 cols; no max-subtraction
        const __half2* __restrict__ h2 = (const __half2*)g_h16;
        float s = 0.f, a0 = 0.f, a1 = 0.f;
        for (int b0i = 0; b0i < d; b0i += 32) {
            int i = b0i + lane;
            float ex = 0.f;
            int sv = 0;
            if (i < d) {
                sv = __ldg(&g_slots[base + i]);
                float evx = __ldg(&g_el[sv]) + ern;
                evx = evx >= 0.f ? evx : 0.2f * evx;
                ex = __expf(evx);
            }
            s += ex;
            int cnt = min(32, d - b0i);
            for (int j = 0; j < cnt; j++) {
                float exj = __shfl_sync(0xFFFFFFFFu, ex, j);
                int   svj = __shfl_sync(0xFFFFFFFFu, sv, j);
                float2 f = __half22float2(h2[(size_t)svj * 32 + lane]);
                a0 = fmaf(exj, f.x, a0);
                a1 = fmaf(exj, f.y, a1);
            }
        }
        #pragma unroll
        for (int o = 16; o; o >>= 1) s += __shfl_xor_sync(0xFFFFFFFFu, s, o);
        float inv = 1.0f / s;
        float2 bv = *(const float2*)(bias + lane * 2);
        float o0 = fmaf(a0, inv, bv.x);
        float o1 = fmaf(a1, inv, bv.y);
        if (RELU) { o0 = fmaxf(o0, 0.f); o1 = fmaxf(o1, 0.f); }
        if (OUT_HALF) {
            __half* oh = (__half*)outv;
            *(__half2*)(oh + (size_t)gw * 64 + lane * 2) = __floats2half2_rn(o0, o1);
        } else {
            float* of = (float*)outv;
            *(float2*)(of + (size_t)gw * 64 + lane * 2) = make_float2(o0, o1);
        }
    }
}

// ---------------- launch ----------------------------------------------------
extern "C" void kernel_launch(void* const* d_in, const int* in_sizes, int n_in,
                              void* d_out, int out_size) {
    const float* features = (const float*)d_in[0];
    // d_in[1] edge_weights: unused (matches reference)
    const int*   src      = (const int*)d_in[2];
    const int*   dst      = (const int*)d_in[3];
    const float* W1       = (const float*)d_in[4];
    const float* attn_l1  = (const float*)d_in[5];
    const float* attn_r1  = (const float*)d_in[6];
    const float* bias1    = (const float*)d_in[7];
    const float* W2       = (const float*)d_in[8];
    const float* attn_l2  = (const float*)d_in[9];
    const float* attn_r2  = (const float*)d_in[10];
    const float* bias2    = (const float*)d_in[11];
    float* out = (float*)d_out;

    __half* g_h16_ptr; cudaGetSymbolAddress((void**)&g_h16_ptr, g_h16);
    __half* g_x2h_ptr; cudaGetSymbolAddress((void**)&g_x2h_ptr, g_x2h);
    uint4*  wf1_ptr;   cudaGetSymbolAddress((void**)&wf1_ptr,   g_wfrag1);
    uint4*  wf2_ptr;   cudaGetSymbolAddress((void**)&wf2_ptr,   g_wfrag2);

    const int NBp = (N_NODES + 255) / 256;   // 391
    const int WARP_GRID = (N_NODES * 32 + 255) / 256;  // 12500
    const int GEMM_GRID = (N_NODES + 63) / 64;         // 1563

    // --- prep (zero degrees + W fragments) ---
    prep_kernel<<<NBp, 256>>>(W1, W2);

    // --- layer 1: GEMM + attn dots + edge bucketing, all in one launch ---
    gemm_attn_kernel<F_IN, true, false><<<GEMM_GRID, 256>>>(
        features, wf1_ptr, attn_l1, attn_r1, g_h16_ptr, src, dst);
    aggregate_kernel<true, true><<<WARP_GRID, 256>>>(bias1, g_x2h_ptr);

    // --- layer 2: fp16-input GEMM (lo(X)=0 -> 2 MMAs/step) ---
    gemm_attn_kernel<F_HID, false, true><<<GEMM_GRID, 256>>>(
        g_x2h_ptr, wf2_ptr, attn_l2, attn_r2, g_h16_ptr, nullptr, nullptr);
    aggregate_kernel<false, false><<<WARP_GRID, 256>>>(bias2, out);
}

// round 17
// speedup vs baseline: 1.0765x; 1.0215x over previous
#include <cuda_runtime.h>
#include <cuda_fp16.h>
#include <math.h>
#include <stdint.h>

// Problem constants (fixed by the dataset)
#define N_NODES 100000
#define N_EDGES 1600000
#define F_IN    128
#define F_HID   64
#define F_OUT   64
#define CAP     64      // max in-degree bucket capacity (P(overflow) ~ 1e-13)

// ---------------- scratch (device globals; no allocations allowed) ----------
__device__ __half g_h16[N_NODES * 64];  // transformed features (gather side, fp16)
__device__ __half g_x2h[N_NODES * 64];  // layer-1 activations (fp16, input to GEMM2)
__device__ float  g_el [N_NODES];
__device__ float  g_er [N_NODES];
__device__ int    g_deg[N_NODES];
__device__ int    g_slots[N_NODES * CAP];  // src ids bucketed by dst
__device__ uint4  g_wfrag1[8 * 8 * 32];    // W1 fp16 hi/lo fragments (k16 chunks)
__device__ uint4  g_wfrag2[4 * 8 * 32];    // W2 fp16 hi/lo fragments

// ---------------- fp16 split helpers ----------------------------------------
__device__ __forceinline__ void split16(float x, __half& h, __half& l) {
    h = __float2half_rn(x);
    l = __float2half_rn(x - __half2float(h));
}

__device__ __forceinline__ uint32_t packh2(__half a, __half b) {
    __half2 p = __halves2half2(a, b);
    return *reinterpret_cast<uint32_t*>(&p);
}

__device__ __forceinline__ uint32_t packf2h(float a, float b) {
    __half2 p = __floats2half2_rn(a, b);
    return *reinterpret_cast<uint32_t*>(&p);
}

// fp16 MMA m16n8k16, fp32 accumulate
__device__ __forceinline__ void mma_f16(float* d, const uint32_t* a, const uint32_t* b) {
    asm volatile(
        "mma.sync.aligned.m16n8k16.row.col.f32.f16.f16.f32 "
        "{%0,%1,%2,%3}, {%4,%5,%6,%7}, {%8,%9}, {%0,%1,%2,%3};"
        : "+f"(d[0]), "+f"(d[1]), "+f"(d[2]), "+f"(d[3])
        : "r"(a[0]), "r"(a[1]), "r"(a[2]), "r"(a[3]), "r"(b[0]), "r"(b[1]));
}

// ---------------- prep: zero degrees + W fragments (fused) ---------------------
__global__ void prep_kernel(const float* __restrict__ W1, const float* __restrict__ W2) {
    int i = blockIdx.x * blockDim.x + threadIdx.x;
    if (i < N_NODES) g_deg[i] = 0;
    if (i < 3072) {
        const float* W; uint4* dstp; int idx;
        if (i < 2048) { W = W1; dstp = g_wfrag1; idx = i; }
        else          { W = W2; dstp = g_wfrag2; idx = i - 2048; }
        int tig = idx & 3;
        int g   = (idx >> 2) & 7;
        int t   = (idx >> 5) & 7;
        int kc  = idx >> 8;
        int k0  = kc * 16 + 2 * tig;
        int n   = t * 8 + g;
        float w0 = W[(k0    ) * 64 + n];
        float w1 = W[(k0 + 1) * 64 + n];
        float w2 = W[(k0 + 8) * 64 + n];
        float w3 = W[(k0 + 9) * 64 + n];
        __half h0, l0, h1, l1, h2, l2, h3, l3;
        split16(w0, h0, l0); split16(w1, h1, l1);
        split16(w2, h2, l2); split16(w3, h3, l3);
        uint4 v;
        v.x = packh2(h0, h1);
        v.y = packh2(h2, h3);
        v.z = packh2(l0, l1);
        v.w = packh2(l2, l3);
        dstp[idx] = v;
    }
}

// ---------------- fused GEMM + attention dots ----------------------------------
// X quantized to fp16 (hi only) in both layers -> 2 MMAs/step (ah*bh + ah*bl).
// W keeps the hi/lo split so W error stays ~2^-22; X-quantization error ~2.4e-4
// matches what the fp16 h-storage already imposes downstream.
// HALF_IN: X already fp16 (layer 2). DO_BUCKET: bucket 1024 edges under MMA loop.
template <int K, bool DO_BUCKET, bool HALF_IN>
__global__ void __launch_bounds__(256, 4)
gemm_attn_kernel(const void* __restrict__ Xv, const uint4* __restrict__ wfrag,
                 const float* __restrict__ attn_l, const float* __restrict__ attn_r,
                 __half* __restrict__ H16,
                 const int* __restrict__ src, const int* __restrict__ dst) {
    constexpr int XS2 = (K == 128) ? 36 : 20;  // uint2 row stride, == 4 mod 16
    __shared__ uint2 xs2[64 * XS2];
    __shared__ float s_al[64], s_ar[64];
    __shared__ float s_el[64][2], s_er[64][2];

    const int tid  = threadIdx.x;
    const int warp = tid >> 5;
    const int lane = tid & 31;
    const int gr   = lane >> 2;
    const int q4   = lane & 3;
    const int rg   = warp >> 1;
    const int ch   = warp & 1;
    const int row0 = blockIdx.x * 64;

    if (tid < 64) { s_al[tid] = attn_l[tid]; s_ar[tid] = attn_r[tid]; }

    if (HALF_IN) {
        // stage fp16 X (K=64): thread = one (row, k16-chunk); pure layout shuffle
        const __half* X = (const __half*)Xv;
        int r  = tid >> 2;
        int kc = tid & 3;
        uint4 u0 = make_uint4(0, 0, 0, 0), u1 = u0;
        if (row0 + r < N_NODES) {
            const uint4* xp = (const uint4*)(X + (size_t)(row0 + r) * 64 + kc * 16);
            u0 = __ldg(xp);
            u1 = __ldg(xp + 1);
        }
        uint4* d4 = (uint4*)&xs2[r * XS2 + kc * 4];
        d4[0] = make_uint4(u0.x, u1.x, u0.y, u1.y);
        d4[1] = make_uint4(u0.z, u1.z, u0.w, u1.w);
    } else {
        // stage fp32 X quantized to fp16 hi (lo dropped); fragment order
        const float* X = (const float*)Xv;
        #pragma unroll
        for (int it = 0; it < K / 32; it++) {
            int item = it * 256 + tid;
            int r   = item / (K / 8);
            int rem = item % (K / 8);
            int kc  = rem >> 1;
            int a   = rem & 1;
            float4 v0 = make_float4(0.f, 0.f, 0.f, 0.f), v1 = v0;
            if (row0 + r < N_NODES) {
                const float* xp = X + (size_t)(row0 + r) * K + kc * 16 + 4 * a;
                v0 = *(const float4*)xp;
                v1 = *(const float4*)(xp + 8);
            }
            uint2 w0, w1;
            w0.x = packf2h(v0.x, v0.y); w0.y = packf2h(v1.x, v1.y);
            w1.x = packf2h(v0.z, v0.w); w1.y = packf2h(v1.z, v1.w);
            int au = r * XS2 + kc * 4 + 2 * a;
            xs2[au]     = w0;
            xs2[au + 1] = w1;
        }
    }
    __syncthreads();

    // edge bucketing for this block's 1024-edge slice (layer 1 only)
    if (DO_BUCKET) {
        int e0 = blockIdx.x * 1024 + tid;
        #pragma unroll
        for (int u = 0; u < 4; u++) {
            int i = e0 + u * 256;
            if (i < N_EDGES) {
                int dd = __ldg(&dst[i]);
                int p = atomicAdd(&g_deg[dd], 1);
                if (p < CAP) g_slots[dd * CAP + p] = __ldg(&src[i]);
            }
        }
    }

    float acc[4][4];
    #pragma unroll
    for (int t = 0; t < 4; t++)
        #pragma unroll
        for (int i = 0; i < 4; i++) acc[t][i] = 0.f;

    #pragma unroll
    for (int kc = 0; kc < K / 16; kc++) {
        int ia = (rg * 16 + gr) * XS2 + kc * 4 + q4;
        uint2 u0 = xs2[ia];
        uint2 u1 = xs2[ia + 8 * XS2];
        uint32_t ah[4] = {u0.x, u1.x, u0.y, u1.y};
        const uint4* wrow = wfrag + kc * 256 + ch * 128 + lane;
        #pragma unroll
        for (int t = 0; t < 4; t++) {
            uint4 wv = __ldg(wrow + t * 32);
            uint32_t bh[2] = {wv.x, wv.y};
            uint32_t bl[2] = {wv.z, wv.w};
            mma_f16(acc[t], ah, bh);
            mma_f16(acc[t], ah, bl);
        }
    }

    const int rl_lo = rg * 16 + gr;
    const int rl_hi = rl_lo + 8;
    const int r_lo  = row0 + rl_lo;
    const int r_hi  = row0 + rl_hi;
    float el_lo = 0.f, er_lo = 0.f, el_hi = 0.f, er_hi = 0.f;
    #pragma unroll
    for (int t = 0; t < 4; t++) {
        int n = ch * 32 + t * 8 + 2 * q4;
        float al0 = s_al[n], al1 = s_al[n + 1];
        float ar0 = s_ar[n], ar1 = s_ar[n + 1];
        el_lo += acc[t][0] * al0 + acc[t][1] * al1;
        er_lo += acc[t][0] * ar0 + acc[t][1] * ar1;
        el_hi += acc[t][2] * al0 + acc[t][3] * al1;
        er_hi += acc[t][2] * ar0 + acc[t][3] * ar1;
        if (r_lo < N_NODES)
            *(__half2*)(H16 + (size_t)r_lo * 64 + n) = __floats2half2_rn(acc[t][0], acc[t][1]);
        if (r_hi < N_NODES)
            *(__half2*)(H16 + (size_t)r_hi * 64 + n) = __floats2half2_rn(acc[t][2], acc[t][3]);
    }
    #pragma unroll
    for (int o = 1; o <= 2; o <<= 1) {
        el_lo += __shfl_xor_sync(0xFFFFFFFFu, el_lo, o);
        er_lo += __shfl_xor_sync(0xFFFFFFFFu, er_lo, o);
        el_hi += __shfl_xor_sync(0xFFFFFFFFu, el_hi, o);
        er_hi += __shfl_xor_sync(0xFFFFFFFFu, er_hi, o);
    }
    if (q4 == 0) {
        s_el[rl_lo][ch] = el_lo; s_er[rl_lo][ch] = er_lo;
        s_el[rl_hi][ch] = el_hi; s_er[rl_hi][ch] = er_hi;
    }
    __syncthreads();
    if (tid < 64 && row0 + tid < N_NODES) {
        g_el[row0 + tid] = s_el[tid][0] + s_el[tid][1];
        g_er[row0 + tid] = s_er[tid][0] + s_er[tid][1];
    }
}

// ---------------- softmax-aggregate: warp per dst node (R14/R16-proven) ---------
// No max-subtraction (softmax shift-invariant; logits |e| <~ 7 << 88).
// OUT_HALF: write results as fp16 (layer-1 activations feeding GEMM2).
template <bool RELU, bool OUT_HALF>
__global__ void aggregate_kernel(const float* __restrict__ bias,
                                 void* __restrict__ outv) {
    int gw   = (blockIdx.x * blockDim.x + threadIdx.x) >> 5;
    int lane = threadIdx.x & 31;
    if (gw >= N_NODES) return;

    const int d = min(g_deg[gw], CAP);
    const int base = gw * CAP;
    const float ern = g_er[gw];

    if (d <= 32) {
        // phase 1: lane = edge index; ex = exp(leaky(el+er)) directly
        int sv = (lane < d) ? __ldg(&g_slots[base + lane]) : 0;
        float ex = 0.f;
        if (lane < d) {
            float ev = __ldg(&g_el[sv]) + ern;
            ev = ev >= 0.f ? ev : 0.2f * ev;
            ex = __expf(ev);
        }

        // phase 2: batches of 16 edges, 4 loads/lane in flight
        const int g = lane >> 3;      // edge subgroup 0..3
        const int cc = lane & 7;      // col octet 0..7
        float a[8];
        #pragma unroll
        for (int u = 0; u < 8; u++) a[u] = 0.f;

        {   // batch 0: edges 0..15 (always; exj=0 pads)
            float exj[4]; int svj[4]; uint4 hv[4];
            #pragma unroll
            for (int u = 0; u < 4; u++) {
                int j = u * 4 + g;
                exj[u] = __shfl_sync(0xFFFFFFFFu, ex, j);
                svj[u] = __shfl_sync(0xFFFFFFFFu, sv, j);
            }
            #pragma unroll
            for (int u = 0; u < 4; u++)
                hv[u] = __ldg((const uint4*)(g_h16 + (size_t)svj[u] * 64) + cc);
            #pragma unroll
            for (int u = 0; u < 4; u++) {
                const __half2* hp = (const __half2*)&hv[u];
                #pragma unroll
                for (int v = 0; v < 4; v++) {
                    float2 f = __half22float2(hp[v]);
                    a[2 * v]     = fmaf(exj[u], f.x, a[2 * v]);
                    a[2 * v + 1] = fmaf(exj[u], f.y, a[2 * v + 1]);
                }
            }
        }
        if (d > 16) {   // batch 1: edges 16..31
            float exj[4]; int svj[4]; uint4 hv[4];
            #pragma unroll
            for (int u = 0; u < 4; u++) {
                int j = 16 + u * 4 + g;
                exj[u] = __shfl_sync(0xFFFFFFFFu, ex, j);
                svj[u] = __shfl_sync(0xFFFFFFFFu, sv, j);
            }
            #pragma unroll
            for (int u = 0; u < 4; u++)
                hv[u] = __ldg((const uint4*)(g_h16 + (size_t)svj[u] * 64) + cc);
            #pragma unroll
            for (int u = 0; u < 4; u++) {
                const __half2* hp = (const __half2*)&hv[u];
                #pragma unroll
                for (int v = 0; v < 4; v++) {
                    float2 f = __half22float2(hp[v]);
                    a[2 * v]     = fmaf(exj[u], f.x, a[2 * v]);
                    a[2 * v + 1] = fmaf(exj[u], f.y, a[2 * v + 1]);
                }
            }
        }
        // combine subgroups (lanes differing in bits 3,4 share the same cols)
        #pragma unroll
        for (int u = 0; u < 8; u++) {
            a[u] += __shfl_xor_sync(0xFFFFFFFFu, a[u], 8);
            a[u] += __shfl_xor_sync(0xFFFFFFFFu, a[u], 16);
        }
        float s = ex;
        #pragma unroll
        for (int o = 16; o; o >>= 1) s += __shfl_xor_sync(0xFFFFFFFFu, s, o);
        float inv = (d > 0) ? 1.0f / s : 0.0f;

        if (g == 0) {   // lanes 0..7 write 8 cols each
            float4 b0 = __ldg((const float4*)bias + cc * 2);
            float4 b1 = __ldg((const float4*)bias + cc * 2 + 1);
            float o0 = fmaf(a[0], inv, b0.x), o1 = fmaf(a[1], inv, b0.y);
            float o2 = fmaf(a[2], inv, b0.z), o3 = fmaf(a[3], inv, b0.w);
            float o4 = fmaf(a[4], inv, b1.x), o5 = fmaf(a[5], inv, b1.y);
            float o6 = fmaf(a[6], inv, b1.z), o7 = fmaf(a[7], inv, b1.w);
            if (RELU) {
                o0 = fmaxf(o0, 0.f); o1 = fmaxf(o1, 0.f);
                o2 = fmaxf(o2, 0.f); o3 = fmaxf(o3, 0.f);
                o4 = fmaxf(o4, 0.f); o5 = fmaxf(o5, 0.f);
                o6 = fmaxf(o6, 0.f); o7 = fmaxf(o7, 0.f);
            }
            if (OUT_HALF) {
                __half* oh = (__half*)outv;
                uint4 w;
                __half2* wp = (__half2*)&w;
                wp[0] = __floats2half2_rn(o0, o1);
                wp[1] = __floats2half2_rn(o2, o3);
                wp[2] = __floats2half2_rn(o4, o5);
                wp[3] = __floats2half2_rn(o6, o7);
                *(uint4*)(oh + (size_t)gw * 64 + cc * 8) = w;
            } else {
                float* of = (float*)outv;
                float4* op = (float4*)(of + (size_t)gw * 64 + cc * 8);
                op[0] = make_float4(o0, o1, o2, o3);
                op[1] = make_float4(o4, o5, o6, o7);
            }
        }
    } else {
        // generic path (rare heavy nodes), lane = 2 cols; no max-subtraction
        const __half2* __restrict__ h2 = (const __half2*)g_h16;
        float s = 0.f, a0 = 0.f, a1 = 0.f;
        for (int b0i = 0; b0i < d; b0i += 32) {
            int i = b0i + lane;
            float ex = 0.f;
            int sv = 0;
            if (i < d) {
                sv = __ldg(&g_slots[base + i]);
                float evx = __ldg(&g_el[sv]) + ern;
                evx = evx >= 0.f ? evx : 0.2f * evx;
                ex = __expf(evx);
            }
            s += ex;
            int cnt = min(32, d - b0i);
            for (int j = 0; j < cnt; j++) {
                float exj = __shfl_sync(0xFFFFFFFFu, ex, j);
                int   svj = __shfl_sync(0xFFFFFFFFu, sv, j);
                float2 f = __half22float2(h2[(size_t)svj * 32 + lane]);
                a0 = fmaf(exj, f.x, a0);
                a1 = fmaf(exj, f.y, a1);
            }
        }
        #pragma unroll
        for (int o = 16; o; o >>= 1) s += __shfl_xor_sync(0xFFFFFFFFu, s, o);
        float inv = 1.0f / s;
        float2 bv = *(const float2*)(bias + lane * 2);
        float o0 = fmaf(a0, inv, bv.x);
        float o1 = fmaf(a1, inv, bv.y);
        if (RELU) { o0 = fmaxf(o0, 0.f); o1 = fmaxf(o1, 0.f); }
        if (OUT_HALF) {
            __half* oh = (__half*)outv;
            *(__half2*)(oh + (size_t)gw * 64 + lane * 2) = __floats2half2_rn(o0, o1);
        } else {
            float* of = (float*)outv;
            *(float2*)(of + (size_t)gw * 64 + lane * 2) = make_float2(o0, o1);
        }
    }
}

// ---------------- launch ----------------------------------------------------
extern "C" void kernel_launch(void* const* d_in, const int* in_sizes, int n_in,
                              void* d_out, int out_size) {
    const float* features = (const float*)d_in[0];
    // d_in[1] edge_weights: unused (matches reference)
    const int*   src      = (const int*)d_in[2];
    const int*   dst      = (const int*)d_in[3];
    const float* W1       = (const float*)d_in[4];
    const float* attn_l1  = (const float*)d_in[5];
    const float* attn_r1  = (const float*)d_in[6];
    const float* bias1    = (const float*)d_in[7];
    const float* W2       = (const float*)d_in[8];
    const float* attn_l2  = (const float*)d_in[9];
    const float* attn_r2  = (const float*)d_in[10];
    const float* bias2    = (const float*)d_in[11];
    float* out = (float*)d_out;

    __half* g_h16_ptr; cudaGetSymbolAddress((void**)&g_h16_ptr, g_h16);
    __half* g_x2h_ptr; cudaGetSymbolAddress((void**)&g_x2h_ptr, g_x2h);
    uint4*  wf1_ptr;   cudaGetSymbolAddress((void**)&wf1_ptr,   g_wfrag1);
    uint4*  wf2_ptr;   cudaGetSymbolAddress((void**)&wf2_ptr,   g_wfrag2);

    const int NBp = (N_NODES + 255) / 256;   // 391
    const int WARP_GRID = (N_NODES * 32 + 255) / 256;  // 12500
    const int GEMM_GRID = (N_NODES + 63) / 64;         // 1563

    // --- prep (zero degrees + W fragments) ---
    prep_kernel<<<NBp, 256>>>(W1, W2);

    // --- layer 1: GEMM (X quantized to fp16, 2 MMAs) + attn dots + bucketing ---
    gemm_attn_kernel<F_IN, true, false><<<GEMM_GRID, 256>>>(
        features, wf1_ptr, attn_l1, attn_r1, g_h16_ptr, src, dst);
    aggregate_kernel<true, true><<<WARP_GRID, 256>>>(bias1, g_x2h_ptr);

    // --- layer 2: fp16-input GEMM (2 MMAs) ---
    gemm_attn_kernel<F_HID, false, true><<<GEMM_GRID, 256>>>(
        g_x2h_ptr, wf2_ptr, attn_l2, attn_r2, g_h16_ptr, nullptr, nullptr);
    aggregate_kernel<false, false><<<WARP_GRID, 256>>>(bias2, out);
}